// round 8
// baseline (speedup 1.0000x reference)
#include <cuda_runtime.h>
#include <cuda_bf16.h>

// S4D: K[h, a+64b] = sum_n ( Qr[n][b]*Pr[n][a] - Qi[n][b]*Pi[n][a] )
//   P[n][a] = 2*Ck_n*w^a,  Q[n][b] = (w^64)^b,  w = exp(dt*A)
//
// Mode-pair f32x2 packing + XOR bank swizzle (col' = col ^ ((n2&7)<<1)).
// R8: 256 threads/block with 4b x 4a tiles -> 32 acc regs/thread,
// __launch_bounds__(256,3) -> 3 blocks (24 warps)/SM for latency hiding.
// (tcgen05 unusable: harness PTX target is sm_103, rejects tcgen05.*)

#define NP 16
#define LL 64

typedef unsigned long long u64;

__device__ __forceinline__ u64 ffma2(u64 a, u64 b, u64 c) {
    u64 d;
    asm("fma.rn.f32x2 %0, %1, %2, %3;" : "=l"(d) : "l"(a), "l"(b), "l"(c));
    return d;
}
__device__ __forceinline__ float f2sum(u64 v) {
    float2 f = *reinterpret_cast<float2*>(&v);
    return f.x + f.y;
}

__global__ __launch_bounds__(256, 3)
void s4d_kernel(const float* __restrict__ log_dt,
                const float* __restrict__ C,
                const float* __restrict__ log_A_real,
                const float* __restrict__ A_imag,
                float* __restrict__ out)
{
    __shared__ __align__(16) float2 PrP[NP][LL];
    __shared__ __align__(16) float2 PiP[NP][LL];
    __shared__ __align__(16) float2 QrP[NP][LL];
    __shared__ __align__(16) float2 QiP[NP][LL];   // holds -qi

    const int h   = blockIdx.x;
    const int tid = threadIdx.x;

    // ---------------- Phase 1: build tables (16 pairs x 16 slices of 4) ----
    {
        const int n2 = tid & 15;
        const int s  = tid >> 4;          // slice 0..15 (4 entries each)
        const int xr = (n2 & 7) << 1;     // column swizzle
        const float dt = expf(log_dt[h]);

        float* PrF = (float*)PrP;
        float* PiF = (float*)PiP;
        float* QrF = (float*)QrP;
        float* QiF = (float*)QiP;

        #pragma unroll 1
        for (int c = 0; c < 2; c++) {
            const int m = 2 * n2 + c;
            const float Ar = -expf(log_A_real[h * 32 + m]);
            const float Ai = A_imag[h * 32 + m];
            const float dr = dt * Ar, di = dt * Ai;

            float er, sn, cs;

            // w = exp(dt*A)
            er = expf(dr); sincosf(di, &sn, &cs);
            const float wr = er * cs, wi = er * sn;

            // P: P0 = 2*C*(w-1)/A, slice start P0*w^{4s}
            {
                const float inv = 1.0f / (Ar * Ar + Ai * Ai);
                const float nr = wr - 1.0f, ni = wi;
                const float gr = (nr * Ar + ni * Ai) * inv;
                const float gi = (ni * Ar - nr * Ai) * inv;
                const float Cr = C[(h * 32 + m) * 2 + 0];
                const float Ci = C[(h * 32 + m) * 2 + 1];
                const float p0r = 2.0f * (Cr * gr - Ci * gi);
                const float p0i = 2.0f * (Cr * gi + Ci * gr);

                const float a0f = (float)(4 * s);
                er = expf(dr * a0f); sincosf(di * a0f, &sn, &cs);
                float pr = p0r * (er * cs) - p0i * (er * sn);
                float pi = p0r * (er * sn) + p0i * (er * cs);

                #pragma unroll
                for (int k = 0; k < 4; k++) {
                    const int idx = (n2 * LL + ((4 * s + k) ^ xr)) * 2 + c;
                    PrF[idx] = pr;
                    PiF[idx] = pi;
                    const float t = pr * wr - pi * wi;
                    pi = pr * wi + pi * wr;
                    pr = t;
                }
            }

            // Q: wJ = w^64, slice start (w^64)^{4s} = exp(256*s*dtA)
            {
                er = expf(64.0f * dr); sincosf(64.0f * di, &sn, &cs);
                const float wJr = er * cs, wJi = er * sn;

                const float b0f = 256.0f * (float)s;
                er = expf(dr * b0f); sincosf(di * b0f, &sn, &cs);
                float qr = er * cs, qi = er * sn;

                #pragma unroll
                for (int k = 0; k < 4; k++) {
                    const int idx = (n2 * LL + ((4 * s + k) ^ xr)) * 2 + c;
                    QrF[idx] =  qr;
                    QiF[idx] = -qi;
                    const float t = qr * wJr - qi * wJi;
                    qi = qr * wJi + qi * wJr;
                    qr = t;
                }
            }
        }
    }
    __syncthreads();

    // ---------------- Phase 2: 64x64 contraction, 4b x 4a tiles ----------
    const int tx = tid & 15;
    const int ty = tid >> 4;          // 0..15
    const int b0 = 4 * ty;
    const int aA = 2 * tx;            // owns a in {aA, aA+1, aA+32, aA+33}

    u64 acc[4][4];
    #pragma unroll
    for (int i = 0; i < 4; i++)
        #pragma unroll
        for (int j = 0; j < 4; j++)
            acc[i][j] = 0ull;

    #pragma unroll
    for (int n2 = 0; n2 < NP; n2++) {
        const int x  = (n2 & 7) << 1;
        const int cA = aA ^ x;        // even; cA+32 covers the high a-pair

        // -------- real half: acc += qr * pr --------
        {
            const ulonglong2 pA = *(const ulonglong2*)&PrP[n2][cA];
            const ulonglong2 pB = *(const ulonglong2*)&PrP[n2][cA + 32];
            const ulonglong2 q0 = *(const ulonglong2*)&QrP[n2][b0 ^ x];
            const ulonglong2 q1 = *(const ulonglong2*)&QrP[n2][(b0 + 2) ^ x];
            const u64 p[4] = {pA.x, pA.y, pB.x, pB.y};
            const u64 q[4] = {q0.x, q0.y, q1.x, q1.y};
            #pragma unroll
            for (int i = 0; i < 4; i++)
                #pragma unroll
                for (int j = 0; j < 4; j++)
                    acc[i][j] = ffma2(q[i], p[j], acc[i][j]);
        }
        // -------- imag half: acc += (-qi) * pi --------
        {
            const ulonglong2 pA = *(const ulonglong2*)&PiP[n2][cA];
            const ulonglong2 pB = *(const ulonglong2*)&PiP[n2][cA + 32];
            const ulonglong2 q0 = *(const ulonglong2*)&QiP[n2][b0 ^ x];
            const ulonglong2 q1 = *(const ulonglong2*)&QiP[n2][(b0 + 2) ^ x];
            const u64 p[4] = {pA.x, pA.y, pB.x, pB.y};
            const u64 q[4] = {q0.x, q0.y, q1.x, q1.y};
            #pragma unroll
            for (int i = 0; i < 4; i++)
                #pragma unroll
                for (int j = 0; j < 4; j++)
                    acc[i][j] = ffma2(q[i], p[j], acc[i][j]);
        }
    }

    // ---------------- Store: reduce mode pairs, STG.64 coalesced ----------
    float* o = out + (size_t)h * (LL * LL);
    #pragma unroll
    for (int i = 0; i < 4; i++) {
        float* row = o + (b0 + i) * LL;
        *reinterpret_cast<float2*>(row + aA) =
            make_float2(f2sum(acc[i][0]), f2sum(acc[i][1]));
        *reinterpret_cast<float2*>(row + aA + 32) =
            make_float2(f2sum(acc[i][2]), f2sum(acc[i][3]));
    }
}

extern "C" void kernel_launch(void* const* d_in, const int* in_sizes, int n_in,
                              void* d_out, int out_size)
{
    const float* log_dt     = (const float*)d_in[0];
    const float* C          = (const float*)d_in[1];
    const float* log_A_real = (const float*)d_in[2];
    const float* A_imag     = (const float*)d_in[3];
    float*       out        = (float*)d_out;

    const int H = in_sizes[0];   // 1024
    s4d_kernel<<<H, 256>>>(log_dt, C, log_A_real, A_imag, out);
}

// round 9
// speedup vs baseline: 1.5456x; 1.5456x over previous
#include <cuda_runtime.h>
#include <cuda_bf16.h>
#include <cstdint>

// S4D via warp-level tensor cores (mma.sync, sm_80-compatible PTX).
//
// Per h:  K[m + 128c] = sum_k QT[c,k] * PT[m,k],   m in [0,128), c in [0,32)
//   k = 2n + {re,im} over 32 modes:
//     PT[m,2n] = Re(2*Ck_n*w_n^m),  PT[m,2n+1] = Im(...)
//     QT[c,2n] = Re((w_n^128)^c),   QT[c,2n+1] = -Im(...)
// GEMM M=32 (c), N=128 (m), K=64: A=QT row-major, B=PT col-major -> exactly
// mma.sync.m16n8k16.row.col. fp32 accumulate in registers.
// Precision: 3x bf16 split (hi*hi + hi*lo + lo*hi) ~ 1e-5 rel.
//
// SMEM k-major tiles with XOR swizzle: 16B chunk index ^= (row & 7), so both
// phase-1 stores (32 lanes span a 128B row) and fragment loads (8 rows x 4
// lanes x 4B) touch all 32 banks exactly once -> conflict-free.

typedef uint32_t u32;

__device__ __forceinline__ u32 swoff(u32 row, u32 kb) {
    // byte offset of element (row, k-byte kb) in a 128B-row swizzled tile
    return row * 128u + ((((kb >> 4) ^ (row & 7u)) << 4) | (kb & 15u));
}

__device__ __forceinline__ void mma_bf16(float* d, const u32* a, u32 b0, u32 b1) {
    asm volatile(
        "mma.sync.aligned.m16n8k16.row.col.f32.bf16.bf16.f32 "
        "{%0,%1,%2,%3}, {%4,%5,%6,%7}, {%8,%9}, {%0,%1,%2,%3};"
        : "+f"(d[0]), "+f"(d[1]), "+f"(d[2]), "+f"(d[3])
        : "r"(a[0]), "r"(a[1]), "r"(a[2]), "r"(a[3]), "r"(b0), "r"(b1));
}

__device__ __forceinline__ void split_store(char* hi, char* lo, u32 off,
                                            float x, float y) {
    __nv_bfloat16 xh = __float2bfloat16(x);
    __nv_bfloat16 yh = __float2bfloat16(y);
    __nv_bfloat16 xl = __float2bfloat16(x - __bfloat162float(xh));
    __nv_bfloat16 yl = __float2bfloat16(y - __bfloat162float(yh));
    __nv_bfloat162 h; h.x = xh; h.y = yh;
    __nv_bfloat162 l; l.x = xl; l.y = yl;
    *reinterpret_cast<__nv_bfloat162*>(hi + off) = h;
    *reinterpret_cast<__nv_bfloat162*>(lo + off) = l;
}

__global__ __launch_bounds__(256)
void s4d_kernel(const float* __restrict__ log_dt,
                const float* __restrict__ C,
                const float* __restrict__ log_A_real,
                const float* __restrict__ A_imag,
                float* __restrict__ out)
{
    __shared__ __align__(128) __nv_bfloat16 sPhi[128 * 64];  // 16 KB  B hi
    __shared__ __align__(128) __nv_bfloat16 sPlo[128 * 64];  // 16 KB  B lo
    __shared__ __align__(128) __nv_bfloat16 sQhi[ 32 * 64];  //  4 KB  A hi
    __shared__ __align__(128) __nv_bfloat16 sQlo[ 32 * 64];  //  4 KB  A lo

    const int h   = blockIdx.x;
    const int tid = threadIdx.x;

    // ---------------- Phase 1: build swizzled bf16 hi/lo tiles ------------
    {
        const int n = tid & 31;          // mode
        const int s = tid >> 5;          // slice 0..7
        const float dt = expf(log_dt[h]);

        const float Ar = -expf(log_A_real[h * 32 + n]);
        const float Ai = A_imag[h * 32 + n];
        const float dr = dt * Ar, di = dt * Ai;

        float er, sn, cs;

        // w = exp(dt*A)
        er = expf(dr); sincosf(di, &sn, &cs);
        const float wr = er * cs, wi = er * sn;

        // P0 = 2*C*(w-1)/A
        const float inv = 1.0f / (Ar * Ar + Ai * Ai);
        const float nr = wr - 1.0f, ni = wi;
        const float gr = (nr * Ar + ni * Ai) * inv;
        const float gi = (ni * Ar - nr * Ai) * inv;
        const float Cr = C[(h * 32 + n) * 2 + 0];
        const float Ci = C[(h * 32 + n) * 2 + 1];
        const float p0r = 2.0f * (Cr * gr - Ci * gi);
        const float p0i = 2.0f * (Cr * gi + Ci * gr);

        char* Ph = (char*)sPhi; char* Pl = (char*)sPlo;
        char* Qh = (char*)sQhi; char* Ql = (char*)sQlo;
        const u32 kb = 4u * (u32)n;      // k-byte of this mode's (re,im) pair

        // PT rows m in [16s, 16s+16): start P0*w^{16s} direct, step by w
        {
            const float m0 = (float)(16 * s);
            er = expf(dr * m0); sincosf(di * m0, &sn, &cs);
            float pr = p0r * (er * cs) - p0i * (er * sn);
            float pi = p0r * (er * sn) + p0i * (er * cs);
            #pragma unroll 4
            for (int k = 0; k < 16; k++) {
                const u32 m = 16 * s + k;
                split_store(Ph, Pl, swoff(m, kb), pr, pi);
                const float t = pr * wr - pi * wi;
                pi = pr * wi + pi * wr;
                pr = t;
            }
        }

        // QT rows c in [4s, 4s+4): step w^128 (direct), start exp(512 s dtA)
        {
            er = expf(128.0f * dr); sincosf(128.0f * di, &sn, &cs);
            const float wCr = er * cs, wCi = er * sn;

            const float c0 = 512.0f * (float)s;
            er = expf(dr * c0); sincosf(di * c0, &sn, &cs);
            float qr = er * cs, qi = er * sn;
            #pragma unroll
            for (int k = 0; k < 4; k++) {
                const u32 c = 4 * s + k;
                split_store(Qh, Ql, swoff(c, kb), qr, -qi);
                const float t = qr * wCr - qi * wCi;
                qi = qr * wCi + qi * wCr;
                qr = t;
            }
        }
    }
    __syncthreads();

    // ---------------- Phase 2: mma.sync contraction ----------------------
    // 8 warps: warp w -> c-tile r0 = 16*(w&1), m-tiles j in [4*(w>>1), +4)
    const int lane = tid & 31;
    const int wrp  = tid >> 5;
    const int gid  = lane >> 2;      // groupID
    const int tig  = lane & 3;       // threadID_in_group
    const int r0   = 16 * (wrp & 1);
    const int jb   = 4 * (wrp >> 1);

    const char* Ph = (const char*)sPhi; const char* Pl = (const char*)sPlo;
    const char* Qh = (const char*)sQhi; const char* Ql = (const char*)sQlo;

    float acc[4][4];
    #pragma unroll
    for (int j = 0; j < 4; j++)
        #pragma unroll
        for (int r = 0; r < 4; r++) acc[j][r] = 0.0f;

    #pragma unroll
    for (int kc = 0; kc < 4; kc++) {
        const u32 kb = 32u * kc + 4u * tig;
        const u32 ra = r0 + gid;

        u32 ahi[4], alo[4];
        ahi[0] = *(const u32*)(Qh + swoff(ra,     kb));
        ahi[1] = *(const u32*)(Qh + swoff(ra + 8, kb));
        ahi[2] = *(const u32*)(Qh + swoff(ra,     kb + 16));
        ahi[3] = *(const u32*)(Qh + swoff(ra + 8, kb + 16));
        alo[0] = *(const u32*)(Ql + swoff(ra,     kb));
        alo[1] = *(const u32*)(Ql + swoff(ra + 8, kb));
        alo[2] = *(const u32*)(Ql + swoff(ra,     kb + 16));
        alo[3] = *(const u32*)(Ql + swoff(ra + 8, kb + 16));

        #pragma unroll
        for (int j = 0; j < 4; j++) {
            const u32 rb = 8u * (jb + j) + gid;
            const u32 bh0 = *(const u32*)(Ph + swoff(rb, kb));
            const u32 bh1 = *(const u32*)(Ph + swoff(rb, kb + 16));
            const u32 bl0 = *(const u32*)(Pl + swoff(rb, kb));
            const u32 bl1 = *(const u32*)(Pl + swoff(rb, kb + 16));

            mma_bf16(acc[j], ahi, bh0, bh1);   // hi*hi
            mma_bf16(acc[j], ahi, bl0, bl1);   // hi*lo
            mma_bf16(acc[j], alo, bh0, bh1);   // lo*hi
        }
    }

    // ---------------- Store D fragments: STG.64, sector-aligned -----------
    // D row = c (r0+gid / +8), D col = m = 8*(jb+j) + 2*tig + {0,1}
    float* o = out + (size_t)h * 4096;
    #pragma unroll
    for (int j = 0; j < 4; j++) {
        const int m = 8 * (jb + j) + 2 * tig;
        const int c = r0 + gid;
        *reinterpret_cast<float2*>(o + c * 128 + m) =
            make_float2(acc[j][0], acc[j][1]);
        *reinterpret_cast<float2*>(o + (c + 8) * 128 + m) =
            make_float2(acc[j][2], acc[j][3]);
    }
}

extern "C" void kernel_launch(void* const* d_in, const int* in_sizes, int n_in,
                              void* d_out, int out_size)
{
    const float* log_dt     = (const float*)d_in[0];
    const float* C          = (const float*)d_in[1];
    const float* log_A_real = (const float*)d_in[2];
    const float* A_imag     = (const float*)d_in[3];
    float*       out        = (float*)d_out;

    const int H = in_sizes[0];   // 1024
    s4d_kernel<<<H, 256>>>(log_dt, C, log_A_real, A_imag, out);
}